// round 4
// baseline (speedup 1.0000x reference)
#include <cuda_runtime.h>
#include <cuda_bf16.h>
#include <cstdint>

// FWHT n=1024 over x[64,1024,512] f32, single pass.
// n = j*32 + i. Phase 1: FWHT_32 over i (registers); one smem transpose;
// Phase 2: FWHT_32 over j (registers). Data as float2, packed f32x2 adds.
//
// CTA = 128 threads = (jt in [0,32)) x (dh in [0,4)), d-tile = 8 floats.
// Each thread: 32 float2 (64 data regs). Smem = 32 KB. 5 CTAs/SM.
// Grid = 64 batches * 64 d-tiles = 4096 CTAs.

#define FW_N 1024
#define FW_D 512
#define FW_THREADS 128
#define FW_SMEM_BYTES (FW_N * 8 * 4)   // 1024 rows * 8 floats = 32 KiB

typedef unsigned long long u64t;

// packed butterfly: (a,b) -> (a+b, a-b), two f32 lanes per instruction
__device__ __forceinline__ void bfly(u64t& a, u64t& b) {
    u64t s, d;
    asm("add.rn.f32x2 %0, %2, %3;\n\t"
        "sub.rn.f32x2 %1, %2, %3;"
        : "=l"(s), "=l"(d)
        : "l"(a), "l"(b));
    a = s; b = d;
}

// smem slot (8-byte units) for element (row = jh*32 + il, float2-col dh).
// XOR swizzle on jh by (il & 3): conflict-free in both transpose directions.
__device__ __forceinline__ uint32_t slot8(uint32_t il, uint32_t jh, uint32_t dh) {
    return (il * 32u + (jh ^ (il & 3u))) * 4u + dh;
}

__global__ __launch_bounds__(FW_THREADS, 5)
void fwht1024_kernel(const float* __restrict__ x, float* __restrict__ y) {
    extern __shared__ u64t buf[];      // 4096 x 8B

    const uint32_t tid = threadIdx.x;
    const uint32_t dh  = tid & 3u;     // float2 column (0..3) of 8-float d-tile
    const uint32_t jt  = tid >> 2;     // 0..31 : j in phase 1 / i in phase 2
    const uint32_t b   = blockIdx.x >> 6;   // 0..63 batch
    const uint32_t dt  = blockIdx.x & 63u;  // 0..63 d-tile

    const size_t base = (size_t)b * (FW_N * FW_D) + dt * 8u + dh * 2u;
    const float2* __restrict__ xin = reinterpret_cast<const float2*>(x + base);
    float2* __restrict__ yout      = reinterpret_cast<float2*>(y + base);
    const int rs = FW_D / 2;           // row stride in float2 (256)

    u64t v[32];

    // ---- load rows n = jt*32 + i (streaming, 32B per 4-lane group) ----
#pragma unroll
    for (int i = 0; i < 32; ++i) {
        float2 t = __ldcs(&xin[(size_t)(jt * 32 + i) * rs]);
        v[i] = *reinterpret_cast<u64t*>(&t);
    }

    // ---- phase 1: FWHT_32 over i ----
#pragma unroll
    for (int h = 1; h < 32; h <<= 1) {
#pragma unroll
        for (int i = 0; i < 32; ++i)
            if ((i & h) == 0) bfly(v[i], v[i | h]);
    }

    // ---- transpose: write element (il=i, jh=jt) ----
#pragma unroll
    for (int i = 0; i < 32; ++i)
        buf[slot8((uint32_t)i, jt, dh)] = v[i];

    __syncthreads();

    // ---- read element (il=jt, jh=j) ----
#pragma unroll
    for (int j = 0; j < 32; ++j)
        v[j] = buf[slot8(jt, (uint32_t)j, dh)];

    // ---- phase 2: FWHT_32 over j ----
#pragma unroll
    for (int h = 1; h < 32; h <<= 1) {
#pragma unroll
        for (int j = 0; j < 32; ++j)
            if ((j & h) == 0) bfly(v[j], v[j | h]);
    }

    // ---- store rows n = j*32 + jt (streaming, coalesced) ----
#pragma unroll
    for (int j = 0; j < 32; ++j) {
        float2 t = *reinterpret_cast<float2*>(&v[j]);
        __stcs(&yout[(size_t)(j * 32 + jt) * rs], t);
    }
}

extern "C" void kernel_launch(void* const* d_in, const int* in_sizes, int n_in,
                              void* d_out, int out_size) {
    const float* x = (const float*)d_in[0];
    float* y = (float*)d_out;

    cudaFuncSetAttribute(fwht1024_kernel,
                         cudaFuncAttributeMaxDynamicSharedMemorySize,
                         FW_SMEM_BYTES);

    dim3 grid(64 * 64);   // 4096 CTAs
    fwht1024_kernel<<<grid, FW_THREADS, FW_SMEM_BYTES>>>(x, y);
}

// round 5
// speedup vs baseline: 1.5081x; 1.5081x over previous
#include <cuda_runtime.h>
#include <cuda_bf16.h>
#include <cstdint>

// FWHT over n=1024 for x[64, 1024, 512] f32, single pass.
// n = j*32 + i. Phase 1: FWHT_32 over i (registers); one smem transpose;
// Phase 2: FWHT_32 over j (registers).
//
// R5 = R2 memory structure (float4 / LDG.128, 64 KiB smem, parity swizzle,
// 3 CTAs/SM) + packed add/sub.rn.f32x2 butterflies (halves fma-pipe work).

#define FW_N 1024
#define FW_D 512
#define FW_DQ 4              // float4 columns per CTA (16 floats of d)
#define FW_THREADS 128
#define FW_SMEM_BYTES (FW_N * FW_DQ * (int)sizeof(ulonglong2))   // 64 KiB

// packed butterfly on a float4 held as ulonglong2: (a,b) -> (a+b, a-b)
__device__ __forceinline__ void bfly4(ulonglong2& a, ulonglong2& b) {
    unsigned long long sx, sy, dx, dy;
    asm("add.rn.f32x2 %0, %4, %6;\n\t"
        "add.rn.f32x2 %1, %5, %7;\n\t"
        "sub.rn.f32x2 %2, %4, %6;\n\t"
        "sub.rn.f32x2 %3, %5, %7;"
        : "=l"(sx), "=l"(sy), "=l"(dx), "=l"(dy)
        : "l"(a.x), "l"(a.y), "l"(b.x), "l"(b.y));
    a.x = sx; a.y = sy;
    b.x = dx; b.y = dy;
}

__global__ __launch_bounds__(FW_THREADS, 3)
void fwht1024_kernel(const float* __restrict__ x, float* __restrict__ y) {
    extern __shared__ ulonglong2 smem[];   // [1024][4] 16B slots, row = 64 B

    const int dq = threadIdx.x & 3;    // 0..3  : float4 column within d-tile
    const int jt = threadIdx.x >> 2;   // 0..31 : j (phase 1) / i (phase 2)
    const int b  = blockIdx.x >> 5;    // 0..63 : batch
    const int dt = blockIdx.x & 31;    // 0..31 : d-tile (16 floats each)

    const size_t base = (size_t)b * FW_N * FW_D + (size_t)dt * 16 + (size_t)dq * 4;
    const ulonglong2* __restrict__ xin =
        reinterpret_cast<const ulonglong2*>(x + base);
    ulonglong2* __restrict__ yout = reinterpret_cast<ulonglong2*>(y + base);
    const int rs = FW_D / 4;           // row stride in 16B units (128)

    ulonglong2 v[32];

    // ---- load rows n = jt*32 + i (streaming, 64B per 4-lane group) ----
#pragma unroll
    for (int i = 0; i < 32; ++i)
        v[i] = __ldcs(&xin[(size_t)(jt * 32 + i) * rs]);

    // ---- phase 1: FWHT_32 over i (packed f32x2) ----
#pragma unroll
    for (int h = 1; h < 32; h <<= 1) {
#pragma unroll
        for (int i = 0; i < 32; ++i)
            if ((i & h) == 0) bfly4(v[i], v[i | h]);
    }

    // ---- transpose via smem, parity swizzle: logical (g, i) -> slot (g, i^(g&1))
    const int wsw = jt & 1;
#pragma unroll
    for (int i = 0; i < 32; ++i)
        smem[(jt * 32 + (i ^ wsw)) * FW_DQ + dq] = v[i];

    __syncthreads();

    const int it = jt;                 // thread's i index in phase 2
#pragma unroll
    for (int j = 0; j < 32; ++j)
        v[j] = smem[(j * 32 + (it ^ (j & 1))) * FW_DQ + dq];

    // ---- phase 2: FWHT_32 over j (packed f32x2) ----
#pragma unroll
    for (int h = 1; h < 32; h <<= 1) {
#pragma unroll
        for (int j = 0; j < 32; ++j)
            if ((j & h) == 0) bfly4(v[j], v[j | h]);
    }

    // ---- store rows n = j*32 + it (streaming, 64B per 4-lane group) ----
#pragma unroll
    for (int j = 0; j < 32; ++j)
        __stcs(&yout[(size_t)(j * 32 + it) * rs], v[j]);
}

extern "C" void kernel_launch(void* const* d_in, const int* in_sizes, int n_in,
                              void* d_out, int out_size) {
    const float* x = (const float*)d_in[0];
    float* y = (float*)d_out;

    cudaFuncSetAttribute(fwht1024_kernel,
                         cudaFuncAttributeMaxDynamicSharedMemorySize,
                         FW_SMEM_BYTES);

    const int batches = 64;
    const int dtiles  = FW_D / 16;    // 32
    dim3 grid(batches * dtiles);      // 2048 CTAs
    fwht1024_kernel<<<grid, FW_THREADS, FW_SMEM_BYTES>>>(x, y);
}

// round 6
// speedup vs baseline: 1.7434x; 1.1560x over previous
#include <cuda_runtime.h>
#include <cuda.h>
#include <cstdint>

// FWHT n=1024 over x[64,1024,512] f32, single pass, TMA-pipelined.
//
// n = 32*m + i. Phase A: FWHT_32 over m (rows 32m+jt, registers);
// smem exchange; Phase B: FWHT_32 over i (rows jt*32+i, registers).
// Persistent CTAs (1/SM), 3 x 64KB smem buffers, TMA loads/stores fully
// async via mbarrier + bulk_group; warps never touch gmem directly.

#define FW_N 1024
#define FW_D 512
#define FW_TW 16                          // tile width in floats (64 B)
#define FW_THREADS 128
#define FW_NTILES (64 * (FW_D / FW_TW))   // 2048
#define FW_TILE_BYTES (FW_N * FW_TW * 4)  // 65536
#define FW_NBUF 3
#define FW_MBAR_OFF (FW_NBUF * FW_TILE_BYTES)
#define FW_SMEM_BYTES (FW_MBAR_OFF + 64)

// ---------------- device helpers ----------------

// packed butterfly on float4-as-ulonglong2: (a,b) -> (a+b, a-b)
__device__ __forceinline__ void bfly4(ulonglong2& a, ulonglong2& b) {
    unsigned long long sx, sy, dx, dy;
    asm("add.rn.f32x2 %0, %4, %6;\n\t"
        "add.rn.f32x2 %1, %5, %7;\n\t"
        "sub.rn.f32x2 %2, %4, %6;\n\t"
        "sub.rn.f32x2 %3, %5, %7;"
        : "=l"(sx), "=l"(sy), "=l"(dx), "=l"(dy)
        : "l"(a.x), "l"(a.y), "l"(b.x), "l"(b.y));
    a.x = sx; a.y = sy;
    b.x = dx; b.y = dy;
}

__device__ __forceinline__ void mbar_init(uint32_t mbar, uint32_t count) {
    asm volatile("mbarrier.init.shared.b64 [%0], %1;" :: "r"(mbar), "r"(count) : "memory");
}
__device__ __forceinline__ void mbar_expect_tx(uint32_t mbar, uint32_t bytes) {
    asm volatile("mbarrier.arrive.expect_tx.shared.b64 _, [%0], %1;"
                 :: "r"(mbar), "r"(bytes) : "memory");
}
__device__ __forceinline__ void mbar_wait(uint32_t mbar, uint32_t parity) {
    uint32_t done;
    asm volatile("{\n\t.reg .pred p;\n\t"
                 "mbarrier.try_wait.parity.acquire.cta.shared::cta.b64 p, [%1], %2;\n\t"
                 "selp.b32 %0, 1, 0, p;\n\t}"
                 : "=r"(done) : "r"(mbar), "r"(parity) : "memory");
    if (!done) {
        asm volatile("{\n\t.reg .pred P1;\n\t"
                     "WL_%=:\n\t"
                     "mbarrier.try_wait.parity.acquire.cta.shared::cta.b64 P1, [%0], %1, 0x989680;\n\t"
                     "@P1 bra.uni WD_%=;\n\t"
                     "bra.uni WL_%=;\n\t"
                     "WD_%=:\n\t}"
                     :: "r"(mbar), "r"(parity) : "memory");
    }
}

__device__ __forceinline__ void tma_load_tile(const CUtensorMap* tm, uint32_t dst,
                                              uint32_t mbar, uint32_t tile) {
    const int c0 = (int)(tile & 31u) * FW_TW;       // d offset (elements)
    const int r0 = (int)(tile >> 5) * FW_N;         // flattened row offset
#pragma unroll
    for (int q = 0; q < 4; ++q) {
        asm volatile(
            "cp.async.bulk.tensor.2d.shared::cta.global.tile.mbarrier::complete_tx::bytes "
            "[%0], [%1, {%2, %3}], [%4];"
            :: "r"(dst + q * 16384), "l"(tm), "r"(c0), "r"(r0 + q * 256), "r"(mbar)
            : "memory");
    }
}

__device__ __forceinline__ void tma_store_tile(const CUtensorMap* tm, uint32_t src,
                                               uint32_t tile) {
    const int c0 = (int)(tile & 31u) * FW_TW;
    const int r0 = (int)(tile >> 5) * FW_N;
#pragma unroll
    for (int q = 0; q < 4; ++q) {
        asm volatile(
            "cp.async.bulk.tensor.2d.global.shared::cta.tile.bulk_group "
            "[%0, {%1, %2}], [%3];"
            :: "l"(tm), "r"(c0), "r"(r0 + q * 256), "r"(src + q * 16384)
            : "memory");
    }
    asm volatile("cp.async.bulk.commit_group;" ::: "memory");
}

template <int N_>
__device__ __forceinline__ void tma_store_wait() {
    asm volatile("cp.async.bulk.wait_group %0;" :: "n"(N_) : "memory");
}

// ---------------- kernel ----------------

__global__ __launch_bounds__(FW_THREADS, 1)
void fwht1024_tma(const __grid_constant__ CUtensorMap tin,
                  const __grid_constant__ CUtensorMap tout) {
    extern __shared__ __align__(1024) unsigned char smem[];
    float4* bufs = reinterpret_cast<float4*>(smem);

    uint32_t smem_u32;
    asm("{ .reg .u64 t; cvta.to.shared.u64 t, %1; cvt.u32.u64 %0, t; }"
        : "=r"(smem_u32) : "l"(smem));
    const uint32_t mbar = smem_u32 + FW_MBAR_OFF;

    const int tid = threadIdx.x;
    const int dq  = tid & 3;          // float4 column within 16-float tile
    const int jt  = tid >> 2;         // 0..31
    const uint32_t o = (uint32_t)(jt & 1);   // phase-B row-parity offset

    if (tid == 0) {
#pragma unroll
        for (int s = 0; s < FW_NBUF; ++s) mbar_init(mbar + 8 * s, 1);
    }
    __syncthreads();

    const uint32_t stride = gridDim.x;

    // prologue: prefetch first tile into slot 0
    if (tid == 0 && blockIdx.x < FW_NTILES) {
        mbar_expect_tx(mbar, FW_TILE_BYTES);
        tma_load_tile(&tin, smem_u32, mbar, blockIdx.x);
    }

    uint32_t phases = 0;   // bit s = parity for next wait on slot s
    uint32_t s = 0;

    for (uint32_t t = blockIdx.x; t < FW_NTILES; t += stride) {
        const uint32_t tn = t + stride;
        const uint32_t s1 = (s + 1 == FW_NBUF) ? 0u : s + 1;

        // prefetch next tile into slot s1 (its old store must be done first)
        if (tid == 0 && tn < FW_NTILES) {
            tma_store_wait<1>();
            mbar_expect_tx(mbar + 8 * s1, FW_TILE_BYTES);
            tma_load_tile(&tin, smem_u32 + s1 * FW_TILE_BYTES, mbar + 8 * s1, tn);
        }

        // wait for current tile data
        mbar_wait(mbar + 8 * s, (phases >> s) & 1u);
        phases ^= 1u << s;

        float4* buf = bufs + s * (FW_TILE_BYTES / 16);
        ulonglong2 v[32];

        // ---- phase A: rows 32m + jt (float4 index = 128m + tid) ----
#pragma unroll
        for (int m = 0; m < 32; ++m) {
            float4 f = buf[128 * m + tid];
            v[m] = *reinterpret_cast<ulonglong2*>(&f);
        }
#pragma unroll
        for (int h = 1; h < 32; h <<= 1) {
#pragma unroll
            for (int m = 0; m < 32; ++m)
                if ((m & h) == 0) bfly4(v[m], v[m | h]);
        }
#pragma unroll
        for (int m = 0; m < 32; ++m)
            buf[128 * m + tid] = *reinterpret_cast<float4*>(&v[m]);

        __syncthreads();

        // ---- phase B: register k holds row jt*32 + (k^o), logical i = k^o ----
        const uint32_t pb = (uint32_t)(jt * 128 + dq);
#pragma unroll
        for (int k = 0; k < 32; ++k) {
            float4 f = buf[pb + (((uint32_t)k ^ o) << 2)];
            v[k] = *reinterpret_cast<ulonglong2*>(&f);
        }
        // stages h = 2,4,8,16 are invariant under the bit-0 relabeling
#pragma unroll
        for (int h = 2; h < 32; h <<= 1) {
#pragma unroll
            for (int k = 0; k < 32; ++k)
                if ((k & h) == 0) bfly4(v[k], v[k | h]);
        }
        // stage h = 1: if o==1, registers (k, k+1) hold logical (k+1, k)
#pragma unroll
        for (int k = 0; k < 32; k += 2) {
            ulonglong2 p = v[k], q = v[k + 1];
            unsigned long long sx, sy, dx, dy, ex, ey;
            asm("add.rn.f32x2 %0, %6, %8;\n\t"
                "add.rn.f32x2 %1, %7, %9;\n\t"
                "sub.rn.f32x2 %2, %6, %8;\n\t"
                "sub.rn.f32x2 %3, %7, %9;\n\t"
                "sub.rn.f32x2 %4, %8, %6;\n\t"
                "sub.rn.f32x2 %5, %9, %7;"
                : "=l"(sx), "=l"(sy), "=l"(dx), "=l"(dy), "=l"(ex), "=l"(ey)
                : "l"(p.x), "l"(p.y), "l"(q.x), "l"(q.y));
            v[k].x     = o ? ex : sx;  v[k].y     = o ? ey : sy;
            v[k + 1].x = o ? sx : dx;  v[k + 1].y = o ? sy : dy;
        }
        // write final values: register k -> row jt*32 + (k^o) (its logical row)
#pragma unroll
        for (int k = 0; k < 32; ++k)
            buf[pb + (((uint32_t)k ^ o) << 2)] = *reinterpret_cast<float4*>(&v[k]);

        // make generic-proxy writes visible to the async proxy, then store
        asm volatile("fence.proxy.async.shared::cta;" ::: "memory");
        __syncthreads();

        if (tid == 0)
            tma_store_tile(&tout, smem_u32 + s * FW_TILE_BYTES, t);

        s = s1;
    }

    if (tid == 0) tma_store_wait<0>();   // flush stores before exit
}

// ---------------- host ----------------

typedef CUresult (*EncodeTiledFn)(
    CUtensorMap*, CUtensorMapDataType, cuuint32_t, void*,
    const cuuint64_t*, const cuuint64_t*, const cuuint32_t*, const cuuint32_t*,
    CUtensorMapInterleave, CUtensorMapSwizzle, CUtensorMapL2promotion,
    CUtensorMapFloatOOBfill);

extern "C" void kernel_launch(void* const* d_in, const int* in_sizes, int n_in,
                              void* d_out, int out_size) {
    void* xp = (void*)d_in[0];
    void* yp = d_out;

    void* fn = nullptr;
    cudaDriverEntryPointQueryResult qr;
    cudaGetDriverEntryPoint("cuTensorMapEncodeTiled", &fn, cudaEnableDefault, &qr);
    EncodeTiledFn encode = (EncodeTiledFn)fn;

    cuuint64_t dims[2]    = {FW_D, (cuuint64_t)64 * FW_N};  // {512, 65536}
    cuuint64_t strides[1] = {FW_D * 4};                     // 2048 B per row
    cuuint32_t box[2]     = {FW_TW, 256};
    cuuint32_t es[2]      = {1, 1};

    CUtensorMap tin, tout;
    encode(&tin, CU_TENSOR_MAP_DATA_TYPE_FLOAT32, 2, xp, dims, strides, box, es,
           CU_TENSOR_MAP_INTERLEAVE_NONE, CU_TENSOR_MAP_SWIZZLE_NONE,
           CU_TENSOR_MAP_L2_PROMOTION_L2_128B, CU_TENSOR_MAP_FLOAT_OOB_FILL_NONE);
    encode(&tout, CU_TENSOR_MAP_DATA_TYPE_FLOAT32, 2, yp, dims, strides, box, es,
           CU_TENSOR_MAP_INTERLEAVE_NONE, CU_TENSOR_MAP_SWIZZLE_NONE,
           CU_TENSOR_MAP_L2_PROMOTION_L2_128B, CU_TENSOR_MAP_FLOAT_OOB_FILL_NONE);

    cudaFuncSetAttribute(fwht1024_tma,
                         cudaFuncAttributeMaxDynamicSharedMemorySize,
                         FW_SMEM_BYTES);

    int sms = 148;
    cudaDeviceGetAttribute(&sms, cudaDevAttrMultiProcessorCount, 0);

    fwht1024_tma<<<sms, FW_THREADS, FW_SMEM_BYTES>>>(tin, tout);
}

// round 7
// speedup vs baseline: 1.7581x; 1.0085x over previous
#include <cuda_runtime.h>
#include <cuda.h>
#include <cstdint>

// FWHT n=1024 over x[64,1024,512] f32, single pass, TMA-pipelined.
//
// R7 = R6 TMA/mbarrier pipeline (3 x 64KB buffers, persistent 1 CTA/SM)
// with 256 threads (8 warps, 2/SMSP) instead of 128: each thread owns a
// float2 column, halving per-warp work and doubling latency hiding.
//
// n = 32*a + b. Phase A: FWHT_32 over a (rows 32a+jt); swizzled smem
// exchange; Phase B: FWHT_32 over b (rows jt*32+b).

#define FW_N 1024
#define FW_D 512
#define FW_TW 16                          // tile width in floats (64 B)
#define FW_THREADS 256
#define FW_NTILES (64 * (FW_D / FW_TW))   // 2048
#define FW_TILE_BYTES (FW_N * FW_TW * 4)  // 65536
#define FW_NBUF 3
#define FW_MBAR_OFF (FW_NBUF * FW_TILE_BYTES)
#define FW_SMEM_BYTES (FW_MBAR_OFF + 64)

typedef unsigned long long u64t;

// packed butterfly on a float2-as-u64: (a,b) -> (a+b, a-b)
__device__ __forceinline__ void bfly(u64t& a, u64t& b) {
    u64t s, d;
    asm("add.rn.f32x2 %0, %2, %3;\n\t"
        "sub.rn.f32x2 %1, %2, %3;"
        : "=l"(s), "=l"(d)
        : "l"(a), "l"(b));
    a = s; b = d;
}

__device__ __forceinline__ void mbar_init(uint32_t mbar, uint32_t count) {
    asm volatile("mbarrier.init.shared.b64 [%0], %1;" :: "r"(mbar), "r"(count) : "memory");
}
__device__ __forceinline__ void mbar_expect_tx(uint32_t mbar, uint32_t bytes) {
    asm volatile("mbarrier.arrive.expect_tx.shared.b64 _, [%0], %1;"
                 :: "r"(mbar), "r"(bytes) : "memory");
}
__device__ __forceinline__ void mbar_wait(uint32_t mbar, uint32_t parity) {
    uint32_t done;
    asm volatile("{\n\t.reg .pred p;\n\t"
                 "mbarrier.try_wait.parity.acquire.cta.shared::cta.b64 p, [%1], %2;\n\t"
                 "selp.b32 %0, 1, 0, p;\n\t}"
                 : "=r"(done) : "r"(mbar), "r"(parity) : "memory");
    if (!done) {
        asm volatile("{\n\t.reg .pred P1;\n\t"
                     "WL_%=:\n\t"
                     "mbarrier.try_wait.parity.acquire.cta.shared::cta.b64 P1, [%0], %1, 0x989680;\n\t"
                     "@P1 bra.uni WD_%=;\n\t"
                     "bra.uni WL_%=;\n\t"
                     "WD_%=:\n\t}"
                     :: "r"(mbar), "r"(parity) : "memory");
    }
}

__device__ __forceinline__ void tma_load_tile(const CUtensorMap* tm, uint32_t dst,
                                              uint32_t mbar, uint32_t tile) {
    const int c0 = (int)(tile & 31u) * FW_TW;       // d offset (elements)
    const int r0 = (int)(tile >> 5) * FW_N;         // flattened row offset
#pragma unroll
    for (int q = 0; q < 4; ++q) {
        asm volatile(
            "cp.async.bulk.tensor.2d.shared::cta.global.tile.mbarrier::complete_tx::bytes "
            "[%0], [%1, {%2, %3}], [%4];"
            :: "r"(dst + q * 16384), "l"(tm), "r"(c0), "r"(r0 + q * 256), "r"(mbar)
            : "memory");
    }
}

__device__ __forceinline__ void tma_store_tile(const CUtensorMap* tm, uint32_t src,
                                               uint32_t tile) {
    const int c0 = (int)(tile & 31u) * FW_TW;
    const int r0 = (int)(tile >> 5) * FW_N;
#pragma unroll
    for (int q = 0; q < 4; ++q) {
        asm volatile(
            "cp.async.bulk.tensor.2d.global.shared::cta.tile.bulk_group "
            "[%0, {%1, %2}], [%3];"
            :: "l"(tm), "r"(c0), "r"(r0 + q * 256), "r"(src + q * 16384)
            : "memory");
    }
    asm volatile("cp.async.bulk.commit_group;" ::: "memory");
}

template <int N_>
__device__ __forceinline__ void tma_store_wait() {
    asm volatile("cp.async.bulk.wait_group %0;" :: "n"(N_) : "memory");
}

// ---------------- kernel ----------------

__global__ __launch_bounds__(FW_THREADS, 1)
void fwht1024_tma(const __grid_constant__ CUtensorMap tin,
                  const __grid_constant__ CUtensorMap tout) {
    extern __shared__ __align__(1024) unsigned char smem[];
    u64t* bufs = reinterpret_cast<u64t*>(smem);   // float2 units

    uint32_t smem_u32;
    asm("{ .reg .u64 t; cvta.to.shared.u64 t, %1; cvt.u32.u64 %0, t; }"
        : "=r"(smem_u32) : "l"(smem));
    const uint32_t mbar = smem_u32 + FW_MBAR_OFF;

    const int tid = threadIdx.x;
    const int dh  = tid & 7;          // float2 column (0..7) within 16-float tile
    const int jt  = tid >> 3;         // 0..31
    const uint32_t jsw = (uint32_t)(jt & 1);   // phase-B load swizzle

    if (tid == 0) {
#pragma unroll
        for (int s = 0; s < FW_NBUF; ++s) mbar_init(mbar + 8 * s, 1);
    }
    __syncthreads();

    const uint32_t stride = gridDim.x;

    // prologue: prefetch first tile into slot 0
    if (tid == 0 && blockIdx.x < FW_NTILES) {
        mbar_expect_tx(mbar, FW_TILE_BYTES);
        tma_load_tile(&tin, smem_u32, mbar, blockIdx.x);
    }

    uint32_t phases = 0;   // bit s = parity for next wait on slot s
    uint32_t s = 0;

    for (uint32_t t = blockIdx.x; t < FW_NTILES; t += stride) {
        const uint32_t tn = t + stride;
        const uint32_t s1 = (s + 1 == FW_NBUF) ? 0u : s + 1;

        // prefetch next tile into slot s1 (its old store must have drained)
        if (tid == 0 && tn < FW_NTILES) {
            tma_store_wait<1>();
            mbar_expect_tx(mbar + 8 * s1, FW_TILE_BYTES);
            tma_load_tile(&tin, smem_u32 + s1 * FW_TILE_BYTES, mbar + 8 * s1, tn);
        }

        // wait for current tile data
        mbar_wait(mbar + 8 * s, (phases >> s) & 1u);
        phases ^= 1u << s;

        u64t* buf = bufs + s * (FW_TILE_BYTES / 8);
        u64t v[32];

        // ---- phase A: rows 32a + jt, a = 0..31 (linear layout from TMA) ----
#pragma unroll
        for (int a = 0; a < 32; ++a)
            v[a] = buf[256 * a + tid];

#pragma unroll
        for (int h = 1; h < 32; h <<= 1) {
#pragma unroll
            for (int a = 0; a < 32; ++a)
                if ((a & h) == 0) bfly(v[a], v[a | h]);
        }

        // store element (a, b=jt) at swizzled slot (a*32 + (jt^(a&1)))*8 + dh
#pragma unroll
        for (int a = 0; a < 32; ++a)
            buf[(a * 32 + (jt ^ (a & 1))) * 8 + dh] = v[a];

        __syncthreads();

        // ---- phase B: element (a=jt, b=i) from slot (jt*32 + (i^jsw))*8+dh ----
        const uint32_t pb = (uint32_t)(jt * 256 + dh);
#pragma unroll
        for (int i = 0; i < 32; ++i)
            v[i] = buf[pb + (((uint32_t)i ^ jsw) << 3)];

#pragma unroll
        for (int h = 1; h < 32; h <<= 1) {
#pragma unroll
            for (int i = 0; i < 32; ++i)
                if ((i & h) == 0) bfly(v[i], v[i | h]);
        }

        // final: row n = jt*32 + i, linear layout for TMA (2-way STS, accepted)
#pragma unroll
        for (int i = 0; i < 32; ++i)
            buf[pb + ((uint32_t)i << 3)] = v[i];

        // make generic-proxy writes visible to the async proxy, then store
        asm volatile("fence.proxy.async.shared::cta;" ::: "memory");
        __syncthreads();

        if (tid == 0)
            tma_store_tile(&tout, smem_u32 + s * FW_TILE_BYTES, t);

        s = s1;
    }

    if (tid == 0) tma_store_wait<0>();   // flush stores before exit
}

// ---------------- host ----------------

typedef CUresult (*EncodeTiledFn)(
    CUtensorMap*, CUtensorMapDataType, cuuint32_t, void*,
    const cuuint64_t*, const cuuint64_t*, const cuuint32_t*, const cuuint32_t*,
    CUtensorMapInterleave, CUtensorMapSwizzle, CUtensorMapL2promotion,
    CUtensorMapFloatOOBfill);

extern "C" void kernel_launch(void* const* d_in, const int* in_sizes, int n_in,
                              void* d_out, int out_size) {
    void* xp = (void*)d_in[0];
    void* yp = d_out;

    void* fn = nullptr;
    cudaDriverEntryPointQueryResult qr;
    cudaGetDriverEntryPoint("cuTensorMapEncodeTiled", &fn, cudaEnableDefault, &qr);
    EncodeTiledFn encode = (EncodeTiledFn)fn;

    cuuint64_t dims[2]    = {FW_D, (cuuint64_t)64 * FW_N};  // {512, 65536}
    cuuint64_t strides[1] = {FW_D * 4};                     // 2048 B per row
    cuuint32_t box[2]     = {FW_TW, 256};
    cuuint32_t es[2]      = {1, 1};

    CUtensorMap tin, tout;
    encode(&tin, CU_TENSOR_MAP_DATA_TYPE_FLOAT32, 2, xp, dims, strides, box, es,
           CU_TENSOR_MAP_INTERLEAVE_NONE, CU_TENSOR_MAP_SWIZZLE_NONE,
           CU_TENSOR_MAP_L2_PROMOTION_L2_128B, CU_TENSOR_MAP_FLOAT_OOB_FILL_NONE);
    encode(&tout, CU_TENSOR_MAP_DATA_TYPE_FLOAT32, 2, yp, dims, strides, box, es,
           CU_TENSOR_MAP_INTERLEAVE_NONE, CU_TENSOR_MAP_SWIZZLE_NONE,
           CU_TENSOR_MAP_L2_PROMOTION_L2_128B, CU_TENSOR_MAP_FLOAT_OOB_FILL_NONE);

    cudaFuncSetAttribute(fwht1024_tma,
                         cudaFuncAttributeMaxDynamicSharedMemorySize,
                         FW_SMEM_BYTES);

    int sms = 148;
    cudaDeviceGetAttribute(&sms, cudaDevAttrMultiProcessorCount, 0);

    fwht1024_tma<<<sms, FW_THREADS, FW_SMEM_BYTES>>>(tin, tout);
}

// round 8
// speedup vs baseline: 1.8283x; 1.0399x over previous
#include <cuda_runtime.h>
#include <cuda.h>
#include <cstdint>

// FWHT n=1024 over x[64,1024,512] f32, single pass, TMA-pipelined.
//
// R8 = R7 (256 threads, 3 x 64KB buffers, persistent 1 CTA/SM) with
// prefetch depth 2: loads for tiles t+1 AND t+2 are in flight while
// computing tile t, giving each load ~2 tile-periods of slack.
//
// n = 32*a + b. Phase A: FWHT_32 over a (rows 32a+jt); swizzled smem
// exchange; Phase B: FWHT_32 over b (rows jt*32+b).

#define FW_N 1024
#define FW_D 512
#define FW_TW 16                          // tile width in floats (64 B)
#define FW_THREADS 256
#define FW_NTILES (64 * (FW_D / FW_TW))   // 2048
#define FW_TILE_BYTES (FW_N * FW_TW * 4)  // 65536
#define FW_NBUF 3
#define FW_MBAR_OFF (FW_NBUF * FW_TILE_BYTES)
#define FW_SMEM_BYTES (FW_MBAR_OFF + 64)

typedef unsigned long long u64t;

// packed butterfly on a float2-as-u64: (a,b) -> (a+b, a-b)
__device__ __forceinline__ void bfly(u64t& a, u64t& b) {
    u64t s, d;
    asm("add.rn.f32x2 %0, %2, %3;\n\t"
        "sub.rn.f32x2 %1, %2, %3;"
        : "=l"(s), "=l"(d)
        : "l"(a), "l"(b));
    a = s; b = d;
}

__device__ __forceinline__ void mbar_init(uint32_t mbar, uint32_t count) {
    asm volatile("mbarrier.init.shared.b64 [%0], %1;" :: "r"(mbar), "r"(count) : "memory");
}
__device__ __forceinline__ void mbar_expect_tx(uint32_t mbar, uint32_t bytes) {
    asm volatile("mbarrier.arrive.expect_tx.shared.b64 _, [%0], %1;"
                 :: "r"(mbar), "r"(bytes) : "memory");
}
__device__ __forceinline__ void mbar_wait(uint32_t mbar, uint32_t parity) {
    uint32_t done;
    asm volatile("{\n\t.reg .pred p;\n\t"
                 "mbarrier.try_wait.parity.acquire.cta.shared::cta.b64 p, [%1], %2;\n\t"
                 "selp.b32 %0, 1, 0, p;\n\t}"
                 : "=r"(done) : "r"(mbar), "r"(parity) : "memory");
    if (!done) {
        asm volatile("{\n\t.reg .pred P1;\n\t"
                     "WL_%=:\n\t"
                     "mbarrier.try_wait.parity.acquire.cta.shared::cta.b64 P1, [%0], %1, 0x989680;\n\t"
                     "@P1 bra.uni WD_%=;\n\t"
                     "bra.uni WL_%=;\n\t"
                     "WD_%=:\n\t}"
                     :: "r"(mbar), "r"(parity) : "memory");
    }
}

__device__ __forceinline__ void tma_load_tile(const CUtensorMap* tm, uint32_t dst,
                                              uint32_t mbar, uint32_t tile) {
    const int c0 = (int)(tile & 31u) * FW_TW;       // d offset (elements)
    const int r0 = (int)(tile >> 5) * FW_N;         // flattened row offset
#pragma unroll
    for (int q = 0; q < 4; ++q) {
        asm volatile(
            "cp.async.bulk.tensor.2d.shared::cta.global.tile.mbarrier::complete_tx::bytes "
            "[%0], [%1, {%2, %3}], [%4];"
            :: "r"(dst + q * 16384), "l"(tm), "r"(c0), "r"(r0 + q * 256), "r"(mbar)
            : "memory");
    }
}

__device__ __forceinline__ void tma_store_tile(const CUtensorMap* tm, uint32_t src,
                                               uint32_t tile) {
    const int c0 = (int)(tile & 31u) * FW_TW;
    const int r0 = (int)(tile >> 5) * FW_N;
#pragma unroll
    for (int q = 0; q < 4; ++q) {
        asm volatile(
            "cp.async.bulk.tensor.2d.global.shared::cta.tile.bulk_group "
            "[%0, {%1, %2}], [%3];"
            :: "l"(tm), "r"(c0), "r"(r0 + q * 256), "r"(src + q * 16384)
            : "memory");
    }
    asm volatile("cp.async.bulk.commit_group;" ::: "memory");
}

template <int N_>
__device__ __forceinline__ void tma_store_wait() {
    asm volatile("cp.async.bulk.wait_group %0;" :: "n"(N_) : "memory");
}

// ---------------- kernel ----------------

__global__ __launch_bounds__(FW_THREADS, 1)
void fwht1024_tma(const __grid_constant__ CUtensorMap tin,
                  const __grid_constant__ CUtensorMap tout) {
    extern __shared__ __align__(1024) unsigned char smem[];
    u64t* bufs = reinterpret_cast<u64t*>(smem);   // float2 units

    uint32_t smem_u32;
    asm("{ .reg .u64 t; cvta.to.shared.u64 t, %1; cvt.u32.u64 %0, t; }"
        : "=r"(smem_u32) : "l"(smem));
    const uint32_t mbar = smem_u32 + FW_MBAR_OFF;

    const int tid = threadIdx.x;
    const int dh  = tid & 7;          // float2 column (0..7) within 16-float tile
    const int jt  = tid >> 3;         // 0..31
    const uint32_t jsw = (uint32_t)(jt & 1);   // phase-B load swizzle

    if (tid == 0) {
#pragma unroll
        for (int s = 0; s < FW_NBUF; ++s) mbar_init(mbar + 8 * s, 1);
    }
    __syncthreads();

    const uint32_t stride = gridDim.x;

    // prologue: prefetch tiles t0 -> slot 0 and t0+stride -> slot 1
    if (tid == 0) {
        if (blockIdx.x < FW_NTILES) {
            mbar_expect_tx(mbar, FW_TILE_BYTES);
            tma_load_tile(&tin, smem_u32, mbar, blockIdx.x);
        }
        if (blockIdx.x + stride < FW_NTILES) {
            mbar_expect_tx(mbar + 8, FW_TILE_BYTES);
            tma_load_tile(&tin, smem_u32 + FW_TILE_BYTES, mbar + 8,
                          blockIdx.x + stride);
        }
    }

    uint32_t phases = 0;   // bit s = parity for next wait on slot s
    uint32_t s = 0;

    for (uint32_t t = blockIdx.x; t < FW_NTILES; t += stride) {
        const uint32_t s1 = (s + 1 >= FW_NBUF) ? s + 1 - FW_NBUF : s + 1;
        const uint32_t s2 = (s + 2 >= FW_NBUF) ? s + 2 - FW_NBUF : s + 2;

        // prefetch tile t+2 into slot s2 (slot s2's old store must drain first)
        const uint32_t t2 = t + 2 * stride;
        if (tid == 0 && t2 < FW_NTILES) {
            tma_store_wait<0>();    // only pending store used slot s2
            mbar_expect_tx(mbar + 8 * s2, FW_TILE_BYTES);
            tma_load_tile(&tin, smem_u32 + s2 * FW_TILE_BYTES, mbar + 8 * s2, t2);
        }

        // wait for current tile data (issued 2 iterations ago)
        mbar_wait(mbar + 8 * s, (phases >> s) & 1u);
        phases ^= 1u << s;

        u64t* buf = bufs + s * (FW_TILE_BYTES / 8);
        u64t v[32];

        // ---- phase A: rows 32a + jt, a = 0..31 (linear layout from TMA) ----
#pragma unroll
        for (int a = 0; a < 32; ++a)
            v[a] = buf[256 * a + tid];

#pragma unroll
        for (int h = 1; h < 32; h <<= 1) {
#pragma unroll
            for (int a = 0; a < 32; ++a)
                if ((a & h) == 0) bfly(v[a], v[a | h]);
        }

        // store element (a, b=jt) at swizzled slot (a*32 + (jt^(a&1)))*8 + dh
#pragma unroll
        for (int a = 0; a < 32; ++a)
            buf[(a * 32 + (jt ^ (a & 1))) * 8 + dh] = v[a];

        __syncthreads();

        // ---- phase B: element (a=jt, b=i) from slot (jt*32 + (i^jsw))*8+dh ----
        const uint32_t pb = (uint32_t)(jt * 256 + dh);
#pragma unroll
        for (int i = 0; i < 32; ++i)
            v[i] = buf[pb + (((uint32_t)i ^ jsw) << 3)];

#pragma unroll
        for (int h = 1; h < 32; h <<= 1) {
#pragma unroll
            for (int i = 0; i < 32; ++i)
                if ((i & h) == 0) bfly(v[i], v[i | h]);
        }

        // final: row n = jt*32 + i, linear layout for TMA (2-way STS, accepted)
#pragma unroll
        for (int i = 0; i < 32; ++i)
            buf[pb + ((uint32_t)i << 3)] = v[i];

        // make generic-proxy writes visible to the async proxy, then store
        asm volatile("fence.proxy.async.shared::cta;" ::: "memory");
        __syncthreads();

        if (tid == 0)
            tma_store_tile(&tout, smem_u32 + s * FW_TILE_BYTES, t);

        s = s1;
    }

    if (tid == 0) tma_store_wait<0>();   // flush stores before exit
}

// ---------------- host ----------------

typedef CUresult (*EncodeTiledFn)(
    CUtensorMap*, CUtensorMapDataType, cuuint32_t, void*,
    const cuuint64_t*, const cuuint64_t*, const cuuint32_t*, const cuuint32_t*,
    CUtensorMapInterleave, CUtensorMapSwizzle, CUtensorMapL2promotion,
    CUtensorMapFloatOOBfill);

extern "C" void kernel_launch(void* const* d_in, const int* in_sizes, int n_in,
                              void* d_out, int out_size) {
    void* xp = (void*)d_in[0];
    void* yp = d_out;

    void* fn = nullptr;
    cudaDriverEntryPointQueryResult qr;
    cudaGetDriverEntryPoint("cuTensorMapEncodeTiled", &fn, cudaEnableDefault, &qr);
    EncodeTiledFn encode = (EncodeTiledFn)fn;

    cuuint64_t dims[2]    = {FW_D, (cuuint64_t)64 * FW_N};  // {512, 65536}
    cuuint64_t strides[1] = {FW_D * 4};                     // 2048 B per row
    cuuint32_t box[2]     = {FW_TW, 256};
    cuuint32_t es[2]      = {1, 1};

    CUtensorMap tin, tout;
    encode(&tin, CU_TENSOR_MAP_DATA_TYPE_FLOAT32, 2, xp, dims, strides, box, es,
           CU_TENSOR_MAP_INTERLEAVE_NONE, CU_TENSOR_MAP_SWIZZLE_NONE,
           CU_TENSOR_MAP_L2_PROMOTION_L2_128B, CU_TENSOR_MAP_FLOAT_OOB_FILL_NONE);
    encode(&tout, CU_TENSOR_MAP_DATA_TYPE_FLOAT32, 2, yp, dims, strides, box, es,
           CU_TENSOR_MAP_INTERLEAVE_NONE, CU_TENSOR_MAP_SWIZZLE_NONE,
           CU_TENSOR_MAP_L2_PROMOTION_L2_128B, CU_TENSOR_MAP_FLOAT_OOB_FILL_NONE);

    cudaFuncSetAttribute(fwht1024_tma,
                         cudaFuncAttributeMaxDynamicSharedMemorySize,
                         FW_SMEM_BYTES);

    int sms = 148;
    cudaDeviceGetAttribute(&sms, cudaDevAttrMultiProcessorCount, 0);

    fwht1024_tma<<<sms, FW_THREADS, FW_SMEM_BYTES>>>(tin, tout);
}